// round 1
// baseline (speedup 1.0000x reference)
#include <cuda_runtime.h>
#include <math.h>

#define N_NODES 50000
#define N_EDGES 800000
#define D_IN    128
#define D1      150
#define D1P     152
#define D2      100
#define D_OUT   64

// ---------------- scratch (device globals: no allocation allowed) ------------
__device__ float g_deg_out[N_NODES];
__device__ float g_deg_in [N_NODES];
__device__ float g_agg[(size_t)N_NODES * D_IN];   // GraphConv aggregation
__device__ float g_h1 [(size_t)N_NODES * D1P];    // ELU(GraphConv) output, padded 152
__device__ float g_p  [(size_t)N_NODES * D2];     // h1 @ Wn (pre-scatter projection)
__device__ float g_np [(size_t)N_NODES * D2];     // segment_sum of p over edges
__device__ float g_h2 [(size_t)N_NODES * D2];     // SAGE output

__device__ __forceinline__ float elu(float v) { return v > 0.f ? v : expm1f(v); }

// ---------------- zeroing (deg, agg, np) -------------------------------------
__global__ void zero_kernel() {
    const long stride = (long)gridDim.x * blockDim.x;
    long i = (long)blockIdx.x * blockDim.x + threadIdx.x;
    float4 z = make_float4(0.f, 0.f, 0.f, 0.f);
    for (long t = i; t < (long)N_NODES * D_IN / 4; t += stride) ((float4*)g_agg)[t] = z;
    for (long t = i; t < (long)N_NODES * D2 / 4; t += stride) ((float4*)g_np)[t] = z;
    for (long t = i; t < N_NODES / 4; t += stride) {
        ((float4*)g_deg_out)[t] = z;
        ((float4*)g_deg_in)[t]  = z;
    }
}

// ---------------- degrees ----------------------------------------------------
__global__ void degree_kernel(const int* __restrict__ src, const int* __restrict__ dst) {
    int i = blockIdx.x * blockDim.x + threadIdx.x;
    if (i < N_EDGES) {
        atomicAdd(&g_deg_out[src[i]], 1.f);
        atomicAdd(&g_deg_in [dst[i]], 1.f);
    }
}

// ---------------- scatter 1: agg[dst] += x[src] * norm_out[src] (128 f) ------
__global__ void scatter1_kernel(const float* __restrict__ x,
                                const int* __restrict__ src, const int* __restrict__ dst) {
    int w    = (blockIdx.x * blockDim.x + threadIdx.x) >> 5;
    int lane = threadIdx.x & 31;
    if (w >= N_EDGES) return;
    int s = src[w], d = dst[w];
    float ns = rsqrtf(fmaxf(g_deg_out[s], 1.f));
    float4 v = ((const float4*)(x + (size_t)s * D_IN))[lane];   // 32 lanes * 16B = 512B row
    float* a = g_agg + (size_t)d * D_IN + lane * 4;
    atomicAdd(a + 0, v.x * ns);
    atomicAdd(a + 1, v.y * ns);
    atomicAdd(a + 2, v.z * ns);
    atomicAdd(a + 3, v.w * ns);
}

// ---------------- GEMM1: h1 = ELU((agg * norm_in) @ W1 + b1)  [N,128]->[N,150]
// 64-row tile, 240 thr, TM=8 x TN=5, cols = cg + 30*j
__global__ __launch_bounds__(240) void gemm1_kernel(const float* __restrict__ W1,
                                                    const float* __restrict__ b1) {
    __shared__ float as[64 * 132];
    int tid = threadIdx.x;
    int row0 = blockIdx.x * 64;
    for (int idx = tid; idx < 64 * (D_IN / 4); idx += 240) {
        int r = idx >> 5, c4 = idx & 31;
        int g = row0 + r;
        float4 v = make_float4(0.f, 0.f, 0.f, 0.f);
        if (g < N_NODES) {
            v = ((const float4*)(g_agg + (size_t)g * D_IN))[c4];
            float nin = rsqrtf(fmaxf(g_deg_in[g], 1.f));
            v.x *= nin; v.y *= nin; v.z *= nin; v.w *= nin;
        }
        *(float4*)&as[r * 132 + (c4 << 2)] = v;
    }
    __syncthreads();
    int cg = tid % 30, rg = tid / 30;
    float acc[8][5];
#pragma unroll
    for (int i = 0; i < 8; i++)
#pragma unroll
        for (int j = 0; j < 5; j++) acc[i][j] = 0.f;

#pragma unroll 4
    for (int k = 0; k < D_IN; k++) {
        float wv[5];
#pragma unroll
        for (int j = 0; j < 5; j++) wv[j] = __ldg(&W1[k * D1 + cg + 30 * j]);
#pragma unroll
        for (int i = 0; i < 8; i++) {
            float av = as[(rg * 8 + i) * 132 + k];
#pragma unroll
            for (int j = 0; j < 5; j++) acc[i][j] = fmaf(av, wv[j], acc[i][j]);
        }
    }
#pragma unroll
    for (int i = 0; i < 8; i++) {
        int g = row0 + rg * 8 + i;
        if (g >= N_NODES) continue;
#pragma unroll
        for (int j = 0; j < 5; j++) {
            int c = cg + 30 * j;
            g_h1[(size_t)g * D1P + c] = elu(acc[i][j] + b1[c]);
        }
    }
}

// ---------------- GEMM2a: p = h1 @ Wn  [N,150]->[N,100] (no bias/act) --------
// 64-row tile, 160 thr, TM=8 x TN=5, cols = cg + 20*j
__global__ __launch_bounds__(160) void gemm2a_kernel(const float* __restrict__ Wn) {
    __shared__ float as[64 * D1P];
    int tid = threadIdx.x;
    int row0 = blockIdx.x * 64;
    for (int idx = tid; idx < 64 * (D1P / 4); idx += 160) {
        int r = idx / 38, c4 = idx % 38;
        int g = row0 + r;
        float4 v = make_float4(0.f, 0.f, 0.f, 0.f);
        if (g < N_NODES) v = ((const float4*)(g_h1 + (size_t)g * D1P))[c4];
        *(float4*)&as[r * D1P + c4 * 4] = v;
    }
    __syncthreads();
    int cg = tid % 20, rg = tid / 20;
    float acc[8][5];
#pragma unroll
    for (int i = 0; i < 8; i++)
#pragma unroll
        for (int j = 0; j < 5; j++) acc[i][j] = 0.f;

#pragma unroll 2
    for (int k = 0; k < D1; k++) {
        float wv[5];
#pragma unroll
        for (int j = 0; j < 5; j++) wv[j] = __ldg(&Wn[k * D2 + cg + 20 * j]);
#pragma unroll
        for (int i = 0; i < 8; i++) {
            float av = as[(rg * 8 + i) * D1P + k];
#pragma unroll
            for (int j = 0; j < 5; j++) acc[i][j] = fmaf(av, wv[j], acc[i][j]);
        }
    }
#pragma unroll
    for (int i = 0; i < 8; i++) {
        int g = row0 + rg * 8 + i;
        if (g >= N_NODES) continue;
#pragma unroll
        for (int j = 0; j < 5; j++) g_p[(size_t)g * D2 + cg + 20 * j] = acc[i][j];
    }
}

// ---------------- scatter 2: np[dst] += p[src]  (100 floats) -----------------
__global__ void scatter2_kernel(const int* __restrict__ src, const int* __restrict__ dst) {
    int w    = (blockIdx.x * blockDim.x + threadIdx.x) >> 5;
    int lane = threadIdx.x & 31;
    if (w >= N_EDGES) return;
    int s = src[w], d = dst[w];
    if (lane >= D2 / 4) return;   // 25 active lanes
    float4 v = ((const float4*)(g_p + (size_t)s * D2))[lane];
    float* a = g_np + (size_t)d * D2 + lane * 4;
    atomicAdd(a + 0, v.x);
    atomicAdd(a + 1, v.y);
    atomicAdd(a + 2, v.z);
    atomicAdd(a + 3, v.w);
}

// ---------------- GEMM2b: h2 = ELU(h1 @ Ws + np/deg_in + b2) -----------------
__global__ __launch_bounds__(160) void gemm2b_kernel(const float* __restrict__ Ws,
                                                     const float* __restrict__ b2) {
    __shared__ float as[64 * D1P];
    int tid = threadIdx.x;
    int row0 = blockIdx.x * 64;
    for (int idx = tid; idx < 64 * (D1P / 4); idx += 160) {
        int r = idx / 38, c4 = idx % 38;
        int g = row0 + r;
        float4 v = make_float4(0.f, 0.f, 0.f, 0.f);
        if (g < N_NODES) v = ((const float4*)(g_h1 + (size_t)g * D1P))[c4];
        *(float4*)&as[r * D1P + c4 * 4] = v;
    }
    __syncthreads();
    int cg = tid % 20, rg = tid / 20;
    float acc[8][5];
#pragma unroll
    for (int i = 0; i < 8; i++)
#pragma unroll
        for (int j = 0; j < 5; j++) acc[i][j] = 0.f;

#pragma unroll 2
    for (int k = 0; k < D1; k++) {
        float wv[5];
#pragma unroll
        for (int j = 0; j < 5; j++) wv[j] = __ldg(&Ws[k * D2 + cg + 20 * j]);
#pragma unroll
        for (int i = 0; i < 8; i++) {
            float av = as[(rg * 8 + i) * D1P + k];
#pragma unroll
            for (int j = 0; j < 5; j++) acc[i][j] = fmaf(av, wv[j], acc[i][j]);
        }
    }
#pragma unroll
    for (int i = 0; i < 8; i++) {
        int g = row0 + rg * 8 + i;
        if (g >= N_NODES) continue;
        float invd = 1.f / fmaxf(g_deg_in[g], 1.f);
#pragma unroll
        for (int j = 0; j < 5; j++) {
            int c = cg + 20 * j;
            float v = acc[i][j] + g_np[(size_t)g * D2 + c] * invd + b2[c];
            g_h2[(size_t)g * D2 + c] = elu(v);
        }
    }
}

// ---------------- GEMM3: out = ELU(h2 @ W3 + b3)  [N,100]->[N,64] ------------
// 64-row tile, 256 thr, TM=4 x TN=4, cols = cg + 16*j
__global__ __launch_bounds__(256) void gemm3_kernel(const float* __restrict__ W3,
                                                    const float* __restrict__ b3,
                                                    float* __restrict__ out) {
    __shared__ float as[64 * D2];
    int tid = threadIdx.x;
    int row0 = blockIdx.x * 64;
    for (int idx = tid; idx < 64 * (D2 / 4); idx += 256) {
        int r = idx / 25, c4 = idx % 25;
        int g = row0 + r;
        float4 v = make_float4(0.f, 0.f, 0.f, 0.f);
        if (g < N_NODES) v = ((const float4*)(g_h2 + (size_t)g * D2))[c4];
        *(float4*)&as[r * D2 + c4 * 4] = v;
    }
    __syncthreads();
    int cg = tid % 16, rg = tid / 16;
    float acc[4][4];
#pragma unroll
    for (int i = 0; i < 4; i++)
#pragma unroll
        for (int j = 0; j < 4; j++) acc[i][j] = 0.f;

#pragma unroll 4
    for (int k = 0; k < D2; k++) {
        float wv[4];
#pragma unroll
        for (int j = 0; j < 4; j++) wv[j] = __ldg(&W3[k * D_OUT + cg + 16 * j]);
#pragma unroll
        for (int i = 0; i < 4; i++) {
            float av = as[(rg * 4 + i) * D2 + k];
#pragma unroll
            for (int j = 0; j < 4; j++) acc[i][j] = fmaf(av, wv[j], acc[i][j]);
        }
    }
#pragma unroll
    for (int i = 0; i < 4; i++) {
        int g = row0 + rg * 4 + i;
        if (g >= N_NODES) continue;
#pragma unroll
        for (int j = 0; j < 4; j++) {
            int c = cg + 16 * j;
            out[(size_t)g * D_OUT + c] = elu(acc[i][j] + b3[c]);
        }
    }
}

// ---------------- launch -----------------------------------------------------
extern "C" void kernel_launch(void* const* d_in, const int* in_sizes, int n_in,
                              void* d_out, int out_size) {
    const float* x  = (const float*)d_in[0];
    const int*   src = (const int*)d_in[1];
    const int*   dst = (const int*)d_in[2];
    const float* W1 = (const float*)d_in[3];
    const float* b1 = (const float*)d_in[4];
    const float* Wn = (const float*)d_in[5];
    const float* Ws = (const float*)d_in[6];
    const float* b2 = (const float*)d_in[7];
    const float* W3 = (const float*)d_in[8];
    const float* b3 = (const float*)d_in[9];
    float* out = (float*)d_out;

    const int ROW_BLOCKS = (N_NODES + 63) / 64;   // 782

    zero_kernel<<<2048, 256>>>();
    degree_kernel<<<(N_EDGES + 255) / 256, 256>>>(src, dst);
    scatter1_kernel<<<N_EDGES / 8, 256>>>(x, src, dst);
    gemm1_kernel<<<ROW_BLOCKS, 240>>>(W1, b1);
    gemm2a_kernel<<<ROW_BLOCKS, 160>>>(Wn);
    scatter2_kernel<<<N_EDGES / 8, 256>>>(src, dst);
    gemm2b_kernel<<<ROW_BLOCKS, 160>>>(Ws, b2);
    gemm3_kernel<<<ROW_BLOCKS, 256>>>(W3, b3, out);
}

// round 3
// speedup vs baseline: 1.6813x; 1.6813x over previous
#include <cuda_runtime.h>
#include <math.h>

#define N_NODES 50000
#define N_EDGES 800000
#define D_IN    128
#define D1      150
#define D1P     152
#define D2      100
#define D_OUT   64
#define NB_SCAN 98   // ceil(50000/512)

// ---------------- scratch (device globals) -----------------------------------
__device__ int   g_deg_out_i[N_NODES];
__device__ int   g_deg_in_i [N_NODES];
__device__ int   g_rowoff[N_NODES];
__device__ int   g_fill  [N_NODES];
__device__ int   g_blksum[128];
__device__ int   g_blkoff[128];
__device__ int   g_csr[N_EDGES];
__device__ float g_norm_out[N_NODES];

__device__ float g_agg[(size_t)N_NODES * D_IN];   // (A x) * norms, ready for W1
__device__ float g_h1 [(size_t)N_NODES * D1P];    // ELU(GraphConv), padded 152
__device__ float g_p  [(size_t)N_NODES * D2];     // h1 @ Wn
__device__ float g_np [(size_t)N_NODES * D2];     // mean of p over in-neighbors
__device__ float g_h2 [(size_t)N_NODES * D2];     // SAGE output

__device__ __forceinline__ float elu(float v) { return v > 0.f ? v : expm1f(v); }

// ---------------- zero the per-node counters ---------------------------------
__global__ void zero_kernel() {
    int stride = gridDim.x * blockDim.x;
    for (int i = blockIdx.x * blockDim.x + threadIdx.x; i < N_NODES; i += stride) {
        g_deg_out_i[i] = 0;
        g_deg_in_i[i]  = 0;
    }
}

// ---------------- degrees (int atomics) --------------------------------------
__global__ void degree_kernel(const int* __restrict__ src, const int* __restrict__ dst) {
    int i = blockIdx.x * blockDim.x + threadIdx.x;
    if (i < N_EDGES) {
        atomicAdd(&g_deg_out_i[src[i]], 1);
        atomicAdd(&g_deg_in_i [dst[i]], 1);
    }
}

// ---------------- CSR build: block sums -> scan -> expand -> bucket ----------
__global__ void blksum_kernel() {
    __shared__ int s[512];
    int idx = blockIdx.x * 512 + threadIdx.x;
    s[threadIdx.x] = (idx < N_NODES) ? g_deg_in_i[idx] : 0;
    __syncthreads();
    for (int off = 256; off > 0; off >>= 1) {
        if (threadIdx.x < off) s[threadIdx.x] += s[threadIdx.x + off];
        __syncthreads();
    }
    if (threadIdx.x == 0) g_blksum[blockIdx.x] = s[0];
}

__global__ void scanblk_kernel() {
    int run = 0;
    for (int b = 0; b < NB_SCAN; b++) { g_blkoff[b] = run; run += g_blksum[b]; }
}

__global__ void expand_kernel() {
    __shared__ int s[512];
    int idx = blockIdx.x * 512 + threadIdx.x;
    int v = (idx < N_NODES) ? g_deg_in_i[idx] : 0;
    s[threadIdx.x] = v;
    __syncthreads();
    for (int off = 1; off < 512; off <<= 1) {
        int t = (threadIdx.x >= off) ? s[threadIdx.x - off] : 0;
        __syncthreads();
        s[threadIdx.x] += t;
        __syncthreads();
    }
    if (idx < N_NODES) {
        int o = g_blkoff[blockIdx.x] + s[threadIdx.x] - v;   // exclusive
        g_rowoff[idx] = o;
        g_fill[idx]   = o;
        g_norm_out[idx] = rsqrtf(fmaxf((float)g_deg_out_i[idx], 1.f));
    }
}

__global__ void bucket_kernel(const int* __restrict__ src, const int* __restrict__ dst) {
    int i = blockIdx.x * blockDim.x + threadIdx.x;
    if (i < N_EDGES) {
        int pos = atomicAdd(&g_fill[dst[i]], 1);
        g_csr[pos] = src[i];
    }
}

// ---------------- gather 1: agg[d] = norm_in[d] * sum x[s]*norm_out[s] -------
// one warp per node, lane handles 4 contiguous floats of the 128-float row
__global__ void gather1_kernel(const float* __restrict__ x) {
    int w    = (blockIdx.x * blockDim.x + threadIdx.x) >> 5;
    int lane = threadIdx.x & 31;
    if (w >= N_NODES) return;
    int beg = g_rowoff[w];
    int cnt = g_deg_in_i[w];
    float4 acc = make_float4(0.f, 0.f, 0.f, 0.f);
    for (int base = 0; base < cnt; base += 32) {
        int idx = base + lane;
        int s = 0; float ns = 0.f;
        if (idx < cnt) { s = g_csr[beg + idx]; ns = g_norm_out[s]; }
        int m = min(32, cnt - base);
        for (int j = 0; j < m; j++) {
            int   sj  = __shfl_sync(0xffffffffu, s,  j);
            float nsj = __shfl_sync(0xffffffffu, ns, j);
            float4 v = __ldg((const float4*)(x + (size_t)sj * D_IN) + lane);
            acc.x = fmaf(v.x, nsj, acc.x);
            acc.y = fmaf(v.y, nsj, acc.y);
            acc.z = fmaf(v.z, nsj, acc.z);
            acc.w = fmaf(v.w, nsj, acc.w);
        }
    }
    float nin = rsqrtf(fmaxf((float)cnt, 1.f));
    acc.x *= nin; acc.y *= nin; acc.z *= nin; acc.w *= nin;
    ((float4*)(g_agg + (size_t)w * D_IN))[lane] = acc;
}

// ---------------- gather 2: np[d] = mean over in-edges of p[s] (100 f) -------
__global__ void gather2_kernel() {
    int w    = (blockIdx.x * blockDim.x + threadIdx.x) >> 5;
    int lane = threadIdx.x & 31;
    if (w >= N_NODES) return;
    int beg = g_rowoff[w];
    int cnt = g_deg_in_i[w];
    bool act = lane < (D2 / 4);   // 25 active data lanes
    float4 acc = make_float4(0.f, 0.f, 0.f, 0.f);
    for (int base = 0; base < cnt; base += 32) {
        int idx = base + lane;
        int s = (idx < cnt) ? g_csr[beg + idx] : 0;
        int m = min(32, cnt - base);
        for (int j = 0; j < m; j++) {
            int sj = __shfl_sync(0xffffffffu, s, j);
            if (act) {
                float4 v = __ldg((const float4*)(g_p + (size_t)sj * D2) + lane);
                acc.x += v.x; acc.y += v.y; acc.z += v.z; acc.w += v.w;
            }
        }
    }
    if (act) {
        float invd = 1.f / fmaxf((float)cnt, 1.f);
        acc.x *= invd; acc.y *= invd; acc.z *= invd; acc.w *= invd;
        ((float4*)(g_np + (size_t)w * D2))[lane] = acc;
    }
}

// ---------------- GEMM1: h1 = ELU(agg @ W1 + b1)  [N,128]->[N,150] -----------
__global__ __launch_bounds__(240) void gemm1_kernel(const float* __restrict__ W1,
                                                    const float* __restrict__ b1) {
    __shared__ float as[64 * 132];
    int tid = threadIdx.x;
    int row0 = blockIdx.x * 64;
    for (int idx = tid; idx < 64 * (D_IN / 4); idx += 240) {
        int r = idx >> 5, c4 = idx & 31;
        int g = row0 + r;
        float4 v = make_float4(0.f, 0.f, 0.f, 0.f);
        if (g < N_NODES) v = ((const float4*)(g_agg + (size_t)g * D_IN))[c4];
        *(float4*)&as[r * 132 + (c4 << 2)] = v;
    }
    __syncthreads();
    int cg = tid % 30, rg = tid / 30;
    float acc[8][5];
#pragma unroll
    for (int i = 0; i < 8; i++)
#pragma unroll
        for (int j = 0; j < 5; j++) acc[i][j] = 0.f;

#pragma unroll 4
    for (int k = 0; k < D_IN; k++) {
        float wv[5];
#pragma unroll
        for (int j = 0; j < 5; j++) wv[j] = __ldg(&W1[k * D1 + cg + 30 * j]);
#pragma unroll
        for (int i = 0; i < 8; i++) {
            float av = as[(rg * 8 + i) * 132 + k];
#pragma unroll
            for (int j = 0; j < 5; j++) acc[i][j] = fmaf(av, wv[j], acc[i][j]);
        }
    }
#pragma unroll
    for (int i = 0; i < 8; i++) {
        int g = row0 + rg * 8 + i;
        if (g >= N_NODES) continue;
#pragma unroll
        for (int j = 0; j < 5; j++) {
            int c = cg + 30 * j;
            g_h1[(size_t)g * D1P + c] = elu(acc[i][j] + b1[c]);
        }
    }
}

// ---------------- GEMM2a: p = h1 @ Wn  [N,150]->[N,100] ----------------------
__global__ __launch_bounds__(160) void gemm2a_kernel(const float* __restrict__ Wn) {
    __shared__ float as[64 * D1P];
    int tid = threadIdx.x;
    int row0 = blockIdx.x * 64;
    for (int idx = tid; idx < 64 * (D1P / 4); idx += 160) {
        int r = idx / 38, c4 = idx % 38;
        int g = row0 + r;
        float4 v = make_float4(0.f, 0.f, 0.f, 0.f);
        if (g < N_NODES) v = ((const float4*)(g_h1 + (size_t)g * D1P))[c4];
        *(float4*)&as[r * D1P + c4 * 4] = v;
    }
    __syncthreads();
    int cg = tid % 20, rg = tid / 20;
    float acc[8][5];
#pragma unroll
    for (int i = 0; i < 8; i++)
#pragma unroll
        for (int j = 0; j < 5; j++) acc[i][j] = 0.f;

#pragma unroll 2
    for (int k = 0; k < D1; k++) {
        float wv[5];
#pragma unroll
        for (int j = 0; j < 5; j++) wv[j] = __ldg(&Wn[k * D2 + cg + 20 * j]);
#pragma unroll
        for (int i = 0; i < 8; i++) {
            float av = as[(rg * 8 + i) * D1P + k];
#pragma unroll
            for (int j = 0; j < 5; j++) acc[i][j] = fmaf(av, wv[j], acc[i][j]);
        }
    }
#pragma unroll
    for (int i = 0; i < 8; i++) {
        int g = row0 + rg * 8 + i;
        if (g >= N_NODES) continue;
#pragma unroll
        for (int j = 0; j < 5; j++) g_p[(size_t)g * D2 + cg + 20 * j] = acc[i][j];
    }
}

// ---------------- GEMM2b: h2 = ELU(h1 @ Ws + np + b2) ------------------------
__global__ __launch_bounds__(160) void gemm2b_kernel(const float* __restrict__ Ws,
                                                     const float* __restrict__ b2) {
    __shared__ float as[64 * D1P];
    int tid = threadIdx.x;
    int row0 = blockIdx.x * 64;
    for (int idx = tid; idx < 64 * (D1P / 4); idx += 160) {
        int r = idx / 38, c4 = idx % 38;
        int g = row0 + r;
        float4 v = make_float4(0.f, 0.f, 0.f, 0.f);
        if (g < N_NODES) v = ((const float4*)(g_h1 + (size_t)g * D1P))[c4];
        *(float4*)&as[r * D1P + c4 * 4] = v;
    }
    __syncthreads();
    int cg = tid % 20, rg = tid / 20;
    float acc[8][5];
#pragma unroll
    for (int i = 0; i < 8; i++)
#pragma unroll
        for (int j = 0; j < 5; j++) acc[i][j] = 0.f;

#pragma unroll 2
    for (int k = 0; k < D1; k++) {
        float wv[5];
#pragma unroll
        for (int j = 0; j < 5; j++) wv[j] = __ldg(&Ws[k * D2 + cg + 20 * j]);
#pragma unroll
        for (int i = 0; i < 8; i++) {
            float av = as[(rg * 8 + i) * D1P + k];
#pragma unroll
            for (int j = 0; j < 5; j++) acc[i][j] = fmaf(av, wv[j], acc[i][j]);
        }
    }
#pragma unroll
    for (int i = 0; i < 8; i++) {
        int g = row0 + rg * 8 + i;
        if (g >= N_NODES) continue;
#pragma unroll
        for (int j = 0; j < 5; j++) {
            int c = cg + 20 * j;
            float v = acc[i][j] + g_np[(size_t)g * D2 + c] + b2[c];
            g_h2[(size_t)g * D2 + c] = elu(v);
        }
    }
}

// ---------------- GEMM3: out = ELU(h2 @ W3 + b3)  [N,100]->[N,64] ------------
__global__ __launch_bounds__(256) void gemm3_kernel(const float* __restrict__ W3,
                                                    const float* __restrict__ b3,
                                                    float* __restrict__ out) {
    __shared__ float as[64 * D2];
    int tid = threadIdx.x;
    int row0 = blockIdx.x * 64;
    for (int idx = tid; idx < 64 * (D2 / 4); idx += 256) {
        int r = idx / 25, c4 = idx % 25;
        int g = row0 + r;
        float4 v = make_float4(0.f, 0.f, 0.f, 0.f);
        if (g < N_NODES) v = ((const float4*)(g_h2 + (size_t)g * D2))[c4];
        *(float4*)&as[r * D2 + c4 * 4] = v;
    }
    __syncthreads();
    int cg = tid % 16, rg = tid / 16;
    float acc[4][4];
#pragma unroll
    for (int i = 0; i < 4; i++)
#pragma unroll
        for (int j = 0; j < 4; j++) acc[i][j] = 0.f;

#pragma unroll 4
    for (int k = 0; k < D2; k++) {
        float wv[4];
#pragma unroll
        for (int j = 0; j < 4; j++) wv[j] = __ldg(&W3[k * D_OUT + cg + 16 * j]);
#pragma unroll
        for (int i = 0; i < 4; i++) {
            float av = as[(rg * 4 + i) * D2 + k];
#pragma unroll
            for (int j = 0; j < 4; j++) acc[i][j] = fmaf(av, wv[j], acc[i][j]);
        }
    }
#pragma unroll
    for (int i = 0; i < 4; i++) {
        int g = row0 + rg * 4 + i;
        if (g >= N_NODES) continue;
#pragma unroll
        for (int j = 0; j < 4; j++) {
            int c = cg + 16 * j;
            out[(size_t)g * D_OUT + c] = elu(acc[i][j] + b3[c]);
        }
    }
}

// ---------------- launch -----------------------------------------------------
extern "C" void kernel_launch(void* const* d_in, const int* in_sizes, int n_in,
                              void* d_out, int out_size) {
    const float* x  = (const float*)d_in[0];
    const int*   src = (const int*)d_in[1];
    const int*   dst = (const int*)d_in[2];
    const float* W1 = (const float*)d_in[3];
    const float* b1 = (const float*)d_in[4];
    const float* Wn = (const float*)d_in[5];
    const float* Ws = (const float*)d_in[6];
    const float* b2 = (const float*)d_in[7];
    const float* W3 = (const float*)d_in[8];
    const float* b3 = (const float*)d_in[9];
    float* out = (float*)d_out;

    const int ROW_BLOCKS = (N_NODES + 63) / 64;     // 782
    const int EDGE_BLOCKS = (N_EDGES + 255) / 256;  // 3125
    const int WARP_BLOCKS = (N_NODES * 32 + 255) / 256;  // 6250

    zero_kernel<<<64, 256>>>();
    degree_kernel<<<EDGE_BLOCKS, 256>>>(src, dst);
    blksum_kernel<<<NB_SCAN, 512>>>();
    scanblk_kernel<<<1, 1>>>();
    expand_kernel<<<NB_SCAN, 512>>>();
    bucket_kernel<<<EDGE_BLOCKS, 256>>>(src, dst);
    gather1_kernel<<<WARP_BLOCKS, 256>>>(x);
    gemm1_kernel<<<ROW_BLOCKS, 240>>>(W1, b1);
    gemm2a_kernel<<<ROW_BLOCKS, 160>>>(Wn);
    gather2_kernel<<<WARP_BLOCKS, 256>>>();
    gemm2b_kernel<<<ROW_BLOCKS, 160>>>(Ws, b2);
    gemm3_kernel<<<ROW_BLOCKS, 256>>>(W3, b3, out);
}